// round 8
// baseline (speedup 1.0000x reference)
#include <cuda_runtime.h>
#include <math.h>

#define CC 256
#define HH 64
#define NPIX (HH*HH)

// ---------------- scratch (no allocations allowed) ----------------
__device__ float g_xs [CC*NPIX];     // pooled input (current scale)
__device__ float g_dw [CC*NPIX];     // dwconv output
__device__ float g_pos[CC*NPIX];     // pos conv output
__device__ float g_qkv[3*CC*NPIX];   // qkv (768, N)
__device__ float g_att[CC*NPIX];     // attention output (pre-upsample)
__device__ float g_cat[3*CC*NPIX];   // concatenated upsampled outputs

// ---------------- avg pool ----------------
__global__ void pool_kernel(const float* __restrict__ x, float* __restrict__ out,
                            int s, int Hs) {
    int idx = blockIdx.x * 256 + threadIdx.x;
    int total = CC * Hs * Hs;
    if (idx >= total) return;
    int xo = idx % Hs, yo = (idx / Hs) % Hs, c = idx / (Hs * Hs);
    const float* xp = x + c * NPIX + (yo * s) * HH + xo * s;
    float sum = 0.f;
    for (int dy = 0; dy < s; dy++)
        for (int dx = 0; dx < s; dx++) sum += xp[dy * HH + dx];
    out[idx] = sum * (1.0f / (s * s));
}

// ---------------- fused depthwise 3x3 (dw + pos), zero pad ----------------
__global__ void dwconv_kernel(const float* __restrict__ xs,
                              const float* __restrict__ dw_w, const float* __restrict__ dw_b,
                              const float* __restrict__ pos_w, const float* __restrict__ pos_b,
                              float* __restrict__ dwout, float* __restrict__ posout,
                              int Hs) {
    int idx = blockIdx.x * 256 + threadIdx.x;
    int x0 = idx % Hs, y0 = (idx / Hs) % Hs, c = idx / (Hs * Hs);
    const float* xp = xs + c * Hs * Hs;
    const float* wd = dw_w + c * 9;
    const float* wp = pos_w + c * 9;
    float a = dw_b[c], p = pos_b[c];
#pragma unroll
    for (int ky = 0; ky < 3; ky++) {
        int y = y0 + ky - 1;
        if ((unsigned)y >= (unsigned)Hs) continue;
#pragma unroll
        for (int kx = 0; kx < 3; kx++) {
            int xx = x0 + kx - 1;
            if ((unsigned)xx >= (unsigned)Hs) continue;
            float v = __ldg(xp + y * Hs + xx);
            a = fmaf(v, wd[ky * 3 + kx], a);
            p = fmaf(v, wp[ky * 3 + kx], p);
        }
    }
    dwout[idx]  = a;
    posout[idx] = p;
}

// ---------------- tiled fp32 GEMM: C[M,N] = W[M,K] * A[K,N] + bias (+pos for q,k) ----
template <bool ADD_POS>
__global__ __launch_bounds__(256)
void gemm_kernel(const float* __restrict__ W, const float* __restrict__ A,
                 const float* __restrict__ bias, const float* __restrict__ pos,
                 float* __restrict__ Cout, int Kd, int N) {
    __shared__ float Wt[16][68];   // [k][m], padded for fp4-aligned conflict-light access
    __shared__ float As[16][64];   // [k][n]
    int tid = threadIdx.x;
    int m0 = blockIdx.y * 64, n0 = blockIdx.x * 64;
    int ty = tid >> 4, tx = tid & 15;
    int wm = tid >> 2, wk4 = (tid & 3) * 4;   // W tile load indices
    int ak = tid >> 4, an4 = (tid & 15) * 4;  // A tile load indices
    float acc[4][4] = {};
    for (int k0 = 0; k0 < Kd; k0 += 16) {
        float4 wv = *(const float4*)(W + (size_t)(m0 + wm) * Kd + k0 + wk4);
        Wt[wk4 + 0][wm] = wv.x; Wt[wk4 + 1][wm] = wv.y;
        Wt[wk4 + 2][wm] = wv.z; Wt[wk4 + 3][wm] = wv.w;
        *(float4*)(&As[ak][an4]) = *(const float4*)(A + (size_t)(k0 + ak) * N + n0 + an4);
        __syncthreads();
#pragma unroll
        for (int k = 0; k < 16; k++) {
            float4 wf = *(const float4*)(&Wt[k][ty * 4]);
            float4 af = *(const float4*)(&As[k][tx * 4]);
            float w_[4] = {wf.x, wf.y, wf.z, wf.w};
            float a_[4] = {af.x, af.y, af.z, af.w};
#pragma unroll
            for (int i = 0; i < 4; i++)
#pragma unroll
                for (int j = 0; j < 4; j++)
                    acc[i][j] = fmaf(w_[i], a_[j], acc[i][j]);
        }
        __syncthreads();
    }
#pragma unroll
    for (int i = 0; i < 4; i++) {
        int m = m0 + ty * 4 + i;
        float b = bias[m];
#pragma unroll
        for (int j = 0; j < 4; j++) {
            int n = n0 + tx * 4 + j;
            float v = acc[i][j] + b;
            if (ADD_POS) { if (m < 512) v += pos[(size_t)(m & 255) * N + n]; }
            Cout[(size_t)m * N + n] = v;
        }
    }
}

// ---------------- flash-style attention, fp32 ----------------
// grid: (N/64, 8 heads), block 256. Q tile 64, K/V tile 64, hd=32.
__global__ __launch_bounds__(256)
void attn_kernel(const float* __restrict__ qkv, float* __restrict__ out, int N) {
    int h  = blockIdx.y;
    int n0 = blockIdx.x * 64;
    int tid = threadIdx.x;

    __shared__ float Qs[32][64];    // [d][n], pre-scaled
    __shared__ float Ks[32][64];    // [d][m]
    __shared__ float Vt[64][34];    // [m][d]
    __shared__ float S [64][65];    // [n][m] scores -> probs; reused as [d][n] output stage
    __shared__ float row_m[64], row_l[64], row_c[64];

    const float scale = 0.17677669529663687f;  // 1/sqrt(32)
    const float* qb = qkv + (size_t)(h * 32) * N + n0;
    const float* kb = qkv + (size_t)(256 + h * 32) * N;
    const float* vb = qkv + (size_t)(512 + h * 32) * N;

    // load Q tile (scaled)
#pragma unroll
    for (int r = 0; r < 2; r++) {
        int idx4 = tid + r * 256;            // 0..511 float4 slots of 32x64
        int d = idx4 >> 4, nq = (idx4 & 15) * 4;
        float4 qv = *(const float4*)(qb + (size_t)d * N + nq);
        qv.x *= scale; qv.y *= scale; qv.z *= scale; qv.w *= scale;
        *(float4*)(&Qs[d][nq]) = qv;
    }
    if (tid < 64) { row_m[tid] = -1e30f; row_l[tid] = 0.f; }

    int ty = tid >> 4, tx = tid & 15;        // O mapping: rows ty*4.., dims tx*2..
    float acc[4][2] = {};

    for (int m0 = 0; m0 < N; m0 += 64) {
        // load K tile and transposed V tile
#pragma unroll
        for (int r = 0; r < 2; r++) {
            int idx4 = tid + r * 256;
            int d = idx4 >> 4, mq = (idx4 & 15) * 4;
            *(float4*)(&Ks[d][mq]) = *(const float4*)(kb + (size_t)d * N + m0 + mq);
            float4 vv = *(const float4*)(vb + (size_t)d * N + m0 + mq);
            Vt[mq + 0][d] = vv.x; Vt[mq + 1][d] = vv.y;
            Vt[mq + 2][d] = vv.z; Vt[mq + 3][d] = vv.w;
        }
        __syncthreads();

        // S = (Q*scale)^T K : 4x4 micro-tile per thread
        {
            float c_[4][4] = {};
#pragma unroll
            for (int d = 0; d < 32; d++) {
                float4 qf = *(const float4*)(&Qs[d][ty * 4]);
                float4 kf = *(const float4*)(&Ks[d][tx * 4]);
                float qa[4] = {qf.x, qf.y, qf.z, qf.w};
                float ka[4] = {kf.x, kf.y, kf.z, kf.w};
#pragma unroll
                for (int i = 0; i < 4; i++)
#pragma unroll
                    for (int j = 0; j < 4; j++)
                        c_[i][j] = fmaf(qa[i], ka[j], c_[i][j]);
            }
#pragma unroll
            for (int i = 0; i < 4; i++)
#pragma unroll
                for (int j = 0; j < 4; j++)
                    S[ty * 4 + i][tx * 4 + j] = c_[i][j];
        }
        __syncthreads();

        // online softmax: 4 lanes per row
        {
            int r = tid >> 2, q = tid & 3;
            float oldm = row_m[r];
            float mx = -1e30f;
#pragma unroll
            for (int j = 0; j < 16; j++) mx = fmaxf(mx, S[r][q * 16 + j]);
            mx = fmaxf(mx, __shfl_xor_sync(0xffffffffu, mx, 1));
            mx = fmaxf(mx, __shfl_xor_sync(0xffffffffu, mx, 2));
            float newm = fmaxf(oldm, mx);
            float sum = 0.f;
#pragma unroll
            for (int j = 0; j < 16; j++) {
                float e = __expf(S[r][q * 16 + j] - newm);
                S[r][q * 16 + j] = e;
                sum += e;
            }
            sum += __shfl_xor_sync(0xffffffffu, sum, 1);
            sum += __shfl_xor_sync(0xffffffffu, sum, 2);
            float corr = __expf(oldm - newm);
            __syncwarp();
            if (q == 0) {
                row_c[r] = corr;
                row_l[r] = row_l[r] * corr + sum;
                row_m[r] = newm;
            }
        }
        __syncthreads();

        // rescale accumulators, then O += P * V^T
#pragma unroll
        for (int i = 0; i < 4; i++) {
            float cr = row_c[ty * 4 + i];
            acc[i][0] *= cr; acc[i][1] *= cr;
        }
#pragma unroll 8
        for (int m = 0; m < 64; m++) {
            float2 vv = *(const float2*)(&Vt[m][tx * 2]);
#pragma unroll
            for (int i = 0; i < 4; i++) {
                float p = S[ty * 4 + i][m];
                acc[i][0] = fmaf(p, vv.x, acc[i][0]);
                acc[i][1] = fmaf(p, vv.y, acc[i][1]);
            }
        }
        __syncthreads();
    }

    // stage output transposed in S ([d][n]) for coalesced global write
#pragma unroll
    for (int i = 0; i < 4; i++) {
        float inv = 1.0f / row_l[ty * 4 + i];
        S[tx * 2 + 0][ty * 4 + i] = acc[i][0] * inv;
        S[tx * 2 + 1][ty * 4 + i] = acc[i][1] * inv;
    }
    __syncthreads();
#pragma unroll
    for (int r = 0; r < 8; r++) {
        int idx = tid + r * 256;           // 0..2047 over 32x64
        int d = idx >> 6, n = idx & 63;
        out[(size_t)(h * 32 + d) * N + n0 + n] = S[d][n];
    }
}

// ---------------- bilinear upsample (jax.image.resize semantics) ----------------
__global__ void upsample_kernel(const float* __restrict__ in, float* __restrict__ out,
                                int s, int Hs) {
    int idx = blockIdx.x * 256 + threadIdx.x;     // over CC*64*64
    int xo = idx & 63, yo = (idx >> 6) & 63, c = idx >> 12;
    float fs = 1.0f / s;
    float fy = (yo + 0.5f) * fs - 0.5f;
    float fx = (xo + 0.5f) * fs - 0.5f;
    float fy0 = floorf(fy), fx0 = floorf(fx);
    float wy = fy - fy0, wx = fx - fx0;
    int y0 = (int)fy0, x0 = (int)fx0;
    int y0c = max(y0, 0), y1c = min(y0 + 1, Hs - 1);
    int x0c = max(x0, 0), x1c = min(x0 + 1, Hs - 1);
    const float* ip = in + (size_t)c * Hs * Hs;
    float v00 = ip[y0c * Hs + x0c], v01 = ip[y0c * Hs + x1c];
    float v10 = ip[y1c * Hs + x0c], v11 = ip[y1c * Hs + x1c];
    float v0 = v00 + (v01 - v00) * wx;
    float v1 = v10 + (v11 - v10) * wx;
    out[idx] = v0 + (v1 - v0) * wy;
}

// ---------------- host launch ----------------
extern "C" void kernel_launch(void* const* d_in, const int* in_sizes, int n_in,
                              void* d_out, int out_size) {
    const float* x     = (const float*)d_in[0];
    const float* dw_w  = (const float*)d_in[1];
    const float* dw_b  = (const float*)d_in[2];
    const float* pw_w  = (const float*)d_in[3];
    const float* pw_b  = (const float*)d_in[4];
    const float* pos_w = (const float*)d_in[5];
    const float* pos_b = (const float*)d_in[6];
    const float* fus_w = (const float*)d_in[7];
    const float* fus_b = (const float*)d_in[8];
    float* out = (float*)d_out;

    float *xs, *dw, *pos, *qkv, *att, *cat;
    cudaGetSymbolAddress((void**)&xs,  g_xs);
    cudaGetSymbolAddress((void**)&dw,  g_dw);
    cudaGetSymbolAddress((void**)&pos, g_pos);
    cudaGetSymbolAddress((void**)&qkv, g_qkv);
    cudaGetSymbolAddress((void**)&att, g_att);
    cudaGetSymbolAddress((void**)&cat, g_cat);

    const int scales[3] = {1, 2, 4};
    for (int i = 0; i < 3; i++) {
        int s  = scales[i];
        int Hs = HH / s;
        int Ns = Hs * Hs;
        const float* src = x;
        if (s > 1) {
            pool_kernel<<<(CC * Ns + 255) / 256, 256>>>(x, xs, s, Hs);
            src = xs;
        }
        dwconv_kernel<<<(CC * Ns) / 256, 256>>>(src,
                                                dw_w + i * CC * 9, dw_b + i * CC,
                                                pos_w + i * CC * 9, pos_b + i * CC,
                                                dw, pos, Hs);
        // QKV: (768, Ns) = pw_w[i](768,256) * dw(256,Ns) + pw_b; q,k += pos
        gemm_kernel<true><<<dim3(Ns / 64, 768 / 64), 256>>>(
            pw_w + (size_t)i * 768 * 256, dw, pw_b + i * 768, pos, qkv, 256, Ns);
        // attention
        float* att_dst = (s == 1) ? cat : att;   // scale-1 output goes straight into cat slot 0
        attn_kernel<<<dim3(Ns / 64, 8), 256>>>(qkv, att_dst, Ns);
        if (s > 1) {
            upsample_kernel<<<(CC * NPIX) / 256, 256>>>(att, cat + (size_t)i * CC * NPIX, s, Hs);
        }
    }
    // fusion: out(256,4096) = fus_w(256,768) * cat(768,4096) + fus_b
    gemm_kernel<false><<<dim3(NPIX / 64, CC / 64), 256>>>(
        fus_w, cat, fus_b, nullptr, out, 3 * CC, NPIX);
}

// round 9
// speedup vs baseline: 1.0879x; 1.0879x over previous
#include <cuda_runtime.h>
#include <math.h>

#define CC 256
#define HH 64
#define NPIX (HH*HH)
typedef unsigned long long u64;

// ---------------- packed f32x2 helpers (Blackwell FFMA2 path) ----------------
__device__ __forceinline__ void ffma2(u64 &d, u64 a, u64 b) {
    asm("fma.rn.f32x2 %0, %1, %2, %0;" : "+l"(d) : "l"(a), "l"(b));
}
__device__ __forceinline__ void fmul2(u64 &d, u64 a) {
    asm("mul.rn.f32x2 %0, %0, %1;" : "+l"(d) : "l"(a));
}
__device__ __forceinline__ u64 pack2(float lo, float hi) {
    u64 r; asm("mov.b64 %0, {%1, %2};" : "=l"(r) : "f"(lo), "f"(hi)); return r;
}
__device__ __forceinline__ float2 unpack2(u64 v) {
    float2 r; asm("mov.b64 {%0, %1}, %2;" : "=f"(r.x), "=f"(r.y) : "l"(v)); return r;
}

// ---------------- FFMA-pipe exp (no MUFU) ----------------
// exp(x) = 2^(x*log2e). Magic-constant round-to-int, degree-6 2^f poly on [-0.5,0.5].
__device__ __forceinline__ float fast_exp(float x) {
    x = fmaxf(x, -87.0f);
    float t = x * 1.4426950408889634f;
    float z = t + 12582912.0f;                       // round-to-nearest into mantissa
    unsigned ip = (unsigned)__float_as_int(z) << 23; // == (n << 23) mod 2^32
    float f = t - (z - 12582912.0f);                 // f in [-0.5, 0.5]
    float p =             1.5402670e-4f;
    p = fmaf(p, f, 1.3333558e-3f);
    p = fmaf(p, f, 9.6181291e-3f);
    p = fmaf(p, f, 5.5504109e-2f);
    p = fmaf(p, f, 2.4022651e-1f);
    p = fmaf(p, f, 6.9314718e-1f);
    p = fmaf(p, f, 1.0f);
    return __uint_as_float(__float_as_uint(p) + ip);
}

// ---------------- scratch (no allocations allowed) ----------------
__device__ float g_xs [CC*NPIX];
__device__ float g_dw [CC*NPIX];
__device__ float g_pos[CC*NPIX];
__device__ float g_qkv[3*CC*NPIX];
__device__ float g_att[CC*NPIX];
__device__ float g_cat[3*CC*NPIX];

// ---------------- avg pool ----------------
__global__ void pool_kernel(const float* __restrict__ x, float* __restrict__ out,
                            int s, int Hs) {
    int idx = blockIdx.x * 256 + threadIdx.x;
    int total = CC * Hs * Hs;
    if (idx >= total) return;
    int xo = idx % Hs, yo = (idx / Hs) % Hs, c = idx / (Hs * Hs);
    const float* xp = x + c * NPIX + (yo * s) * HH + xo * s;
    float sum = 0.f;
    for (int dy = 0; dy < s; dy++)
        for (int dx = 0; dx < s; dx++) sum += xp[dy * HH + dx];
    out[idx] = sum * (1.0f / (s * s));
}

// ---------------- fused depthwise 3x3 (dw + pos), zero pad ----------------
__global__ void dwconv_kernel(const float* __restrict__ xs,
                              const float* __restrict__ dw_w, const float* __restrict__ dw_b,
                              const float* __restrict__ pos_w, const float* __restrict__ pos_b,
                              float* __restrict__ dwout, float* __restrict__ posout,
                              int Hs) {
    int idx = blockIdx.x * 256 + threadIdx.x;
    int x0 = idx % Hs, y0 = (idx / Hs) % Hs, c = idx / (Hs * Hs);
    const float* xp = xs + c * Hs * Hs;
    const float* wd = dw_w + c * 9;
    const float* wp = pos_w + c * 9;
    float a = dw_b[c], p = pos_b[c];
#pragma unroll
    for (int ky = 0; ky < 3; ky++) {
        int y = y0 + ky - 1;
        if ((unsigned)y >= (unsigned)Hs) continue;
#pragma unroll
        for (int kx = 0; kx < 3; kx++) {
            int xx = x0 + kx - 1;
            if ((unsigned)xx >= (unsigned)Hs) continue;
            float v = __ldg(xp + y * Hs + xx);
            a = fmaf(v, wd[ky * 3 + kx], a);
            p = fmaf(v, wp[ky * 3 + kx], p);
        }
    }
    dwout[idx]  = a;
    posout[idx] = p;
}

// ---------------- tiled GEMM with FFMA2: C[M,N] = W[M,K]*A[K,N] + bias (+pos) ----
template <bool ADD_POS>
__global__ __launch_bounds__(256)
void gemm_kernel(const float* __restrict__ W, const float* __restrict__ A,
                 const float* __restrict__ bias, const float* __restrict__ pos,
                 float* __restrict__ Cout, int Kd, int N) {
    __shared__ __align__(16) float Wt[16][68];   // [k][m]
    __shared__ __align__(16) float As[16][64];   // [k][n]
    int tid = threadIdx.x;
    int m0 = blockIdx.y * 64, n0 = blockIdx.x * 64;
    int ty = tid >> 4, tx = tid & 15;
    int wm = tid >> 2, wk4 = (tid & 3) * 4;
    int ak = tid >> 4, an4 = (tid & 15) * 4;
    u64 c2[2][4] = {};                           // pairs along m
    for (int k0 = 0; k0 < Kd; k0 += 16) {
        float4 wv = *(const float4*)(W + (size_t)(m0 + wm) * Kd + k0 + wk4);
        Wt[wk4 + 0][wm] = wv.x; Wt[wk4 + 1][wm] = wv.y;
        Wt[wk4 + 2][wm] = wv.z; Wt[wk4 + 3][wm] = wv.w;
        *(float4*)(&As[ak][an4]) = *(const float4*)(A + (size_t)(k0 + ak) * N + n0 + an4);
        __syncthreads();
#pragma unroll
        for (int k = 0; k < 16; k++) {
            ulonglong2 ww = *(const ulonglong2*)(&Wt[k][ty * 4]);  // (m0,m1),(m2,m3)
            float4 af = *(const float4*)(&As[k][tx * 4]);
            u64 a0 = pack2(af.x, af.x), a1 = pack2(af.y, af.y);
            u64 a2 = pack2(af.z, af.z), a3 = pack2(af.w, af.w);
            ffma2(c2[0][0], ww.x, a0); ffma2(c2[0][1], ww.x, a1);
            ffma2(c2[0][2], ww.x, a2); ffma2(c2[0][3], ww.x, a3);
            ffma2(c2[1][0], ww.y, a0); ffma2(c2[1][1], ww.y, a1);
            ffma2(c2[1][2], ww.y, a2); ffma2(c2[1][3], ww.y, a3);
        }
        __syncthreads();
    }
#pragma unroll
    for (int ipair = 0; ipair < 2; ipair++) {
#pragma unroll
        for (int j = 0; j < 4; j++) {
            float2 v = unpack2(c2[ipair][j]);
            int n = n0 + tx * 4 + j;
            float vv[2] = {v.x, v.y};
#pragma unroll
            for (int hh = 0; hh < 2; hh++) {
                int m = m0 + ty * 4 + ipair * 2 + hh;
                float val = vv[hh] + bias[m];
                if (ADD_POS) { if (m < 512) val += pos[(size_t)(m & 255) * N + n]; }
                Cout[(size_t)m * N + n] = val;
            }
        }
    }
}

// ---------------- flash attention, FFMA2 GEMMs + register softmax ----------------
// grid: (N/64, 8 heads), block 256. Q tile 64, K/V tile 64, hd=32.
__global__ __launch_bounds__(256)
void attn_kernel(const float* __restrict__ qkv, float* __restrict__ out, int N) {
    int h  = blockIdx.y;
    int n0 = blockIdx.x * 64;
    int tid = threadIdx.x;

    __shared__ __align__(16) float Qs[32][64];   // [d][n], pre-scaled
    __shared__ __align__(16) float Ks[32][64];   // [d][m]
    __shared__ __align__(16) float Vs[32][68];   // [d][m] (no transpose)
    __shared__ __align__(16) float S [64][68];   // probs [n][m]; reused for output staging

    const float scale = 0.17677669529663687f;    // 1/sqrt(32)
    const float* qb = qkv + (size_t)(h * 32) * N + n0;
    const float* kb = qkv + (size_t)(256 + h * 32) * N;
    const float* vb = qkv + (size_t)(512 + h * 32) * N;

#pragma unroll
    for (int r = 0; r < 2; r++) {
        int idx4 = tid + r * 256;
        int d = idx4 >> 4, nq = (idx4 & 15) * 4;
        float4 qv = *(const float4*)(qb + (size_t)d * N + nq);
        qv.x *= scale; qv.y *= scale; qv.z *= scale; qv.w *= scale;
        *(float4*)(&Qs[d][nq]) = qv;
    }

    int ty = tid >> 4, tx = tid & 15;   // rows ty*4+i; dims tx and tx+16
    float m_r[4] = {-1e30f, -1e30f, -1e30f, -1e30f};
    float l_r[4] = {0.f, 0.f, 0.f, 0.f};
    u64 acc2[4][2] = {};                // [row i][d-half], pairs along m (reduction)

    for (int m0 = 0; m0 < N; m0 += 64) {
#pragma unroll
        for (int r = 0; r < 2; r++) {
            int idx4 = tid + r * 256;
            int d = idx4 >> 4, mq = (idx4 & 15) * 4;
            *(float4*)(&Ks[d][mq]) = *(const float4*)(kb + (size_t)d * N + m0 + mq);
            *(float4*)(&Vs[d][mq]) = *(const float4*)(vb + (size_t)d * N + m0 + mq);
        }
        __syncthreads();

        // ---- S = Q^T K (pairs along query-row) ----
        u64 c2[2][4] = {};
#pragma unroll
        for (int d = 0; d < 32; d++) {
            ulonglong2 qq = *(const ulonglong2*)(&Qs[d][ty * 4]);  // (q0,q1),(q2,q3)
            float4 kf = *(const float4*)(&Ks[d][tx * 4]);
            u64 k0 = pack2(kf.x, kf.x), k1 = pack2(kf.y, kf.y);
            u64 k2 = pack2(kf.z, kf.z), k3 = pack2(kf.w, kf.w);
            ffma2(c2[0][0], qq.x, k0); ffma2(c2[0][1], qq.x, k1);
            ffma2(c2[0][2], qq.x, k2); ffma2(c2[0][3], qq.x, k3);
            ffma2(c2[1][0], qq.y, k0); ffma2(c2[1][1], qq.y, k1);
            ffma2(c2[1][2], qq.y, k2); ffma2(c2[1][3], qq.y, k3);
        }
        float c[4][4];
#pragma unroll
        for (int ipair = 0; ipair < 2; ipair++)
#pragma unroll
            for (int j = 0; j < 4; j++) {
                float2 v = unpack2(c2[ipair][j]);
                c[ipair * 2 + 0][j] = v.x;
                c[ipair * 2 + 1][j] = v.y;
            }

        // ---- register softmax: row r spread over 16 lanes (tx) ----
        float tm[4];
#pragma unroll
        for (int i = 0; i < 4; i++)
            tm[i] = fmaxf(fmaxf(c[i][0], c[i][1]), fmaxf(c[i][2], c[i][3]));
#pragma unroll
        for (int off = 1; off < 16; off <<= 1) {
#pragma unroll
            for (int i = 0; i < 4; i++)
                tm[i] = fmaxf(tm[i], __shfl_xor_sync(0xffffffffu, tm[i], off));
        }
        float corr[4];
#pragma unroll
        for (int i = 0; i < 4; i++) {
            float newm = fmaxf(m_r[i], tm[i]);
            corr[i] = fast_exp(m_r[i] - newm);
            m_r[i] = newm;
        }
#pragma unroll
        for (int i = 0; i < 4; i++)
#pragma unroll
            for (int j = 0; j < 4; j++)
                c[i][j] = fast_exp(c[i][j] - m_r[i]);
        float ts[4];
#pragma unroll
        for (int i = 0; i < 4; i++)
            ts[i] = (c[i][0] + c[i][1]) + (c[i][2] + c[i][3]);
#pragma unroll
        for (int off = 1; off < 16; off <<= 1) {
#pragma unroll
            for (int i = 0; i < 4; i++)
                ts[i] += __shfl_xor_sync(0xffffffffu, ts[i], off);
        }
#pragma unroll
        for (int i = 0; i < 4; i++) {
            l_r[i] = l_r[i] * corr[i] + ts[i];
            u64 cd = pack2(corr[i], corr[i]);
            fmul2(acc2[i][0], cd);
            fmul2(acc2[i][1], cd);
            *(float4*)(&S[ty * 4 + i][tx * 4]) = make_float4(c[i][0], c[i][1], c[i][2], c[i][3]);
        }
        __syncthreads();

        // ---- O += P V^T (pairs along m, fully packed both operands) ----
#pragma unroll
        for (int m4 = 0; m4 < 16; m4++) {
            ulonglong2 va  = *(const ulonglong2*)(&Vs[tx     ][m4 * 4]);
            ulonglong2 vb2 = *(const ulonglong2*)(&Vs[tx + 16][m4 * 4]);
#pragma unroll
            for (int i = 0; i < 4; i++) {
                ulonglong2 pp = *(const ulonglong2*)(&S[ty * 4 + i][m4 * 4]);
                ffma2(acc2[i][0], pp.x, va.x);  ffma2(acc2[i][0], pp.y, va.y);
                ffma2(acc2[i][1], pp.x, vb2.x); ffma2(acc2[i][1], pp.y, vb2.y);
            }
        }
        __syncthreads();
    }

    // ---- finalize: horizontal add, normalize, stage transposed, coalesced store ----
#pragma unroll
    for (int i = 0; i < 4; i++) {
        float inv = 1.0f / l_r[i];
        float2 s0 = unpack2(acc2[i][0]);
        float2 s1 = unpack2(acc2[i][1]);
        S[tx     ][ty * 4 + i] = (s0.x + s0.y) * inv;
        S[tx + 16][ty * 4 + i] = (s1.x + s1.y) * inv;
    }
    __syncthreads();
#pragma unroll
    for (int r = 0; r < 8; r++) {
        int idx = tid + r * 256;
        int d = idx >> 6, n = idx & 63;
        out[(size_t)(h * 32 + d) * N + n0 + n] = S[d][n];
    }
}

// ---------------- bilinear upsample (jax.image.resize semantics) ----------------
__global__ void upsample_kernel(const float* __restrict__ in, float* __restrict__ out,
                                int s, int Hs) {
    int idx = blockIdx.x * 256 + threadIdx.x;
    int xo = idx & 63, yo = (idx >> 6) & 63, c = idx >> 12;
    float fs = 1.0f / s;
    float fy = (yo + 0.5f) * fs - 0.5f;
    float fx = (xo + 0.5f) * fs - 0.5f;
    float fy0 = floorf(fy), fx0 = floorf(fx);
    float wy = fy - fy0, wx = fx - fx0;
    int y0 = (int)fy0, x0 = (int)fx0;
    int y0c = max(y0, 0), y1c = min(y0 + 1, Hs - 1);
    int x0c = max(x0, 0), x1c = min(x0 + 1, Hs - 1);
    const float* ip = in + (size_t)c * Hs * Hs;
    float v00 = ip[y0c * Hs + x0c], v01 = ip[y0c * Hs + x1c];
    float v10 = ip[y1c * Hs + x0c], v11 = ip[y1c * Hs + x1c];
    float v0 = v00 + (v01 - v00) * wx;
    float v1 = v10 + (v11 - v10) * wx;
    out[idx] = v0 + (v1 - v0) * wy;
}

// ---------------- host launch ----------------
extern "C" void kernel_launch(void* const* d_in, const int* in_sizes, int n_in,
                              void* d_out, int out_size) {
    const float* x     = (const float*)d_in[0];
    const float* dw_w  = (const float*)d_in[1];
    const float* dw_b  = (const float*)d_in[2];
    const float* pw_w  = (const float*)d_in[3];
    const float* pw_b  = (const float*)d_in[4];
    const float* pos_w = (const float*)d_in[5];
    const float* pos_b = (const float*)d_in[6];
    const float* fus_w = (const float*)d_in[7];
    const float* fus_b = (const float*)d_in[8];
    float* out = (float*)d_out;

    float *xs, *dw, *pos, *qkv, *att, *cat;
    cudaGetSymbolAddress((void**)&xs,  g_xs);
    cudaGetSymbolAddress((void**)&dw,  g_dw);
    cudaGetSymbolAddress((void**)&pos, g_pos);
    cudaGetSymbolAddress((void**)&qkv, g_qkv);
    cudaGetSymbolAddress((void**)&att, g_att);
    cudaGetSymbolAddress((void**)&cat, g_cat);

    const int scales[3] = {1, 2, 4};
    for (int i = 0; i < 3; i++) {
        int s  = scales[i];
        int Hs = HH / s;
        int Ns = Hs * Hs;
        const float* src = x;
        if (s > 1) {
            pool_kernel<<<(CC * Ns + 255) / 256, 256>>>(x, xs, s, Hs);
            src = xs;
        }
        dwconv_kernel<<<(CC * Ns) / 256, 256>>>(src,
                                                dw_w + i * CC * 9, dw_b + i * CC,
                                                pos_w + i * CC * 9, pos_b + i * CC,
                                                dw, pos, Hs);
        gemm_kernel<true><<<dim3(Ns / 64, 768 / 64), 256>>>(
            pw_w + (size_t)i * 768 * 256, dw, pw_b + i * 768, pos, qkv, 256, Ns);
        float* att_dst = (s == 1) ? cat : att;
        attn_kernel<<<dim3(Ns / 64, 8), 256>>>(qkv, att_dst, Ns);
        if (s > 1) {
            upsample_kernel<<<(CC * NPIX) / 256, 256>>>(att, cat + (size_t)i * CC * NPIX, s, Hs);
        }
    }
    gemm_kernel<false><<<dim3(NPIX / 64, CC / 64), 256>>>(
        fus_w, cat, fus_b, nullptr, out, 3 * CC, NPIX);
}

// round 10
// speedup vs baseline: 1.0885x; 1.0005x over previous
#include <cuda_runtime.h>
#include <math.h>

#define CC 256
#define HH 64
#define NPIX (HH*HH)
typedef unsigned long long u64;

// ---------------- packed f32x2 helpers (Blackwell FFMA2 path) ----------------
__device__ __forceinline__ void ffma2(u64 &d, u64 a, u64 b) {
    asm("fma.rn.f32x2 %0, %1, %2, %0;" : "+l"(d) : "l"(a), "l"(b));
}
__device__ __forceinline__ void fmul2(u64 &d, u64 a) {
    asm("mul.rn.f32x2 %0, %0, %1;" : "+l"(d) : "l"(a));
}
__device__ __forceinline__ u64 pack2(float lo, float hi) {
    u64 r; asm("mov.b64 %0, {%1, %2};" : "=l"(r) : "f"(lo), "f"(hi)); return r;
}
__device__ __forceinline__ float2 unpack2(u64 v) {
    float2 r; asm("mov.b64 {%0, %1}, %2;" : "=f"(r.x), "=f"(r.y) : "l"(v)); return r;
}

// ---------------- FFMA-pipe exp (no MUFU) ----------------
// exp(x) = 2^(x*log2e). Magic-constant round-to-int, degree-6 2^f poly on [-0.5,0.5].
__device__ __forceinline__ float fast_exp(float x) {
    x = fmaxf(x, -87.0f);
    float t = x * 1.4426950408889634f;
    float z = t + 12582912.0f;                       // round-to-nearest into mantissa
    unsigned ip = (unsigned)__float_as_int(z) << 23; // == (n << 23) mod 2^32
    float f = t - (z - 12582912.0f);                 // f in [-0.5, 0.5]
    float p =             1.5402670e-4f;
    p = fmaf(p, f, 1.3333558e-3f);
    p = fmaf(p, f, 9.6181291e-3f);
    p = fmaf(p, f, 5.5504109e-2f);
    p = fmaf(p, f, 2.4022651e-1f);
    p = fmaf(p, f, 6.9314718e-1f);
    p = fmaf(p, f, 1.0f);
    return __uint_as_float(__float_as_uint(p) + ip);
}

// ---------------- scratch (no allocations allowed) ----------------
__device__ float g_xs [CC*NPIX];
__device__ float g_dw [CC*NPIX];
__device__ float g_pos[CC*NPIX];
__device__ float g_qkv[3*CC*NPIX];
__device__ float g_att[CC*NPIX];
__device__ float g_cat[3*CC*NPIX];

// ---------------- avg pool ----------------
__global__ void pool_kernel(const float* __restrict__ x, float* __restrict__ out,
                            int s, int Hs) {
    int idx = blockIdx.x * 256 + threadIdx.x;
    int total = CC * Hs * Hs;
    if (idx >= total) return;
    int xo = idx % Hs, yo = (idx / Hs) % Hs, c = idx / (Hs * Hs);
    const float* xp = x + c * NPIX + (yo * s) * HH + xo * s;
    float sum = 0.f;
    for (int dy = 0; dy < s; dy++)
        for (int dx = 0; dx < s; dx++) sum += xp[dy * HH + dx];
    out[idx] = sum * (1.0f / (s * s));
}

// ---------------- fused depthwise 3x3 (dw + pos), zero pad ----------------
__global__ void dwconv_kernel(const float* __restrict__ xs,
                              const float* __restrict__ dw_w, const float* __restrict__ dw_b,
                              const float* __restrict__ pos_w, const float* __restrict__ pos_b,
                              float* __restrict__ dwout, float* __restrict__ posout,
                              int Hs) {
    int idx = blockIdx.x * 256 + threadIdx.x;
    int x0 = idx % Hs, y0 = (idx / Hs) % Hs, c = idx / (Hs * Hs);
    const float* xp = xs + c * Hs * Hs;
    const float* wd = dw_w + c * 9;
    const float* wp = pos_w + c * 9;
    float a = dw_b[c], p = pos_b[c];
#pragma unroll
    for (int ky = 0; ky < 3; ky++) {
        int y = y0 + ky - 1;
        if ((unsigned)y >= (unsigned)Hs) continue;
#pragma unroll
        for (int kx = 0; kx < 3; kx++) {
            int xx = x0 + kx - 1;
            if ((unsigned)xx >= (unsigned)Hs) continue;
            float v = __ldg(xp + y * Hs + xx);
            a = fmaf(v, wd[ky * 3 + kx], a);
            p = fmaf(v, wp[ky * 3 + kx], p);
        }
    }
    dwout[idx]  = a;
    posout[idx] = p;
}

// ---------------- tiled GEMM with FFMA2: C[M,N] = W[M,K]*A[K,N] + bias (+pos) ----
template <bool ADD_POS>
__global__ __launch_bounds__(256)
void gemm_kernel(const float* __restrict__ W, const float* __restrict__ A,
                 const float* __restrict__ bias, const float* __restrict__ pos,
                 float* __restrict__ Cout, int Kd, int N) {
    __shared__ __align__(16) float Wt[16][68];   // [k][m]
    __shared__ __align__(16) float As[16][64];   // [k][n]
    int tid = threadIdx.x;
    int m0 = blockIdx.y * 64, n0 = blockIdx.x * 64;
    int ty = tid >> 4, tx = tid & 15;
    int wm = tid >> 2, wk4 = (tid & 3) * 4;
    int ak = tid >> 4, an4 = (tid & 15) * 4;
    u64 c2[2][4] = {};                           // pairs along m
    for (int k0 = 0; k0 < Kd; k0 += 16) {
        float4 wv = *(const float4*)(W + (size_t)(m0 + wm) * Kd + k0 + wk4);
        Wt[wk4 + 0][wm] = wv.x; Wt[wk4 + 1][wm] = wv.y;
        Wt[wk4 + 2][wm] = wv.z; Wt[wk4 + 3][wm] = wv.w;
        *(float4*)(&As[ak][an4]) = *(const float4*)(A + (size_t)(k0 + ak) * N + n0 + an4);
        __syncthreads();
#pragma unroll
        for (int k = 0; k < 16; k++) {
            ulonglong2 ww = *(const ulonglong2*)(&Wt[k][ty * 4]);  // (m0,m1),(m2,m3)
            float4 af = *(const float4*)(&As[k][tx * 4]);
            u64 a0 = pack2(af.x, af.x), a1 = pack2(af.y, af.y);
            u64 a2 = pack2(af.z, af.z), a3 = pack2(af.w, af.w);
            ffma2(c2[0][0], ww.x, a0); ffma2(c2[0][1], ww.x, a1);
            ffma2(c2[0][2], ww.x, a2); ffma2(c2[0][3], ww.x, a3);
            ffma2(c2[1][0], ww.y, a0); ffma2(c2[1][1], ww.y, a1);
            ffma2(c2[1][2], ww.y, a2); ffma2(c2[1][3], ww.y, a3);
        }
        __syncthreads();
    }
#pragma unroll
    for (int ipair = 0; ipair < 2; ipair++) {
#pragma unroll
        for (int j = 0; j < 4; j++) {
            float2 v = unpack2(c2[ipair][j]);
            int n = n0 + tx * 4 + j;
            float vv[2] = {v.x, v.y};
#pragma unroll
            for (int hh = 0; hh < 2; hh++) {
                int m = m0 + ty * 4 + ipair * 2 + hh;
                float val = vv[hh] + bias[m];
                if (ADD_POS) { if (m < 512) val += pos[(size_t)(m & 255) * N + n]; }
                Cout[(size_t)m * N + n] = val;
            }
        }
    }
}

// ---------------- flash attention, FFMA2 GEMMs + register softmax ----------------
// grid: (N/64, 8 heads), block 256. Q tile 64, K/V tile 64, hd=32.
__global__ __launch_bounds__(256)
void attn_kernel(const float* __restrict__ qkv, float* __restrict__ out, int N) {
    int h  = blockIdx.y;
    int n0 = blockIdx.x * 64;
    int tid = threadIdx.x;

    __shared__ __align__(16) float Qs[32][64];   // [d][n], pre-scaled
    __shared__ __align__(16) float Ks[32][64];   // [d][m]
    __shared__ __align__(16) float Vs[32][68];   // [d][m] (no transpose)
    __shared__ __align__(16) float S [64][68];   // probs [n][m]; reused for output staging

    const float scale = 0.17677669529663687f;    // 1/sqrt(32)
    const float* qb = qkv + (size_t)(h * 32) * N + n0;
    const float* kb = qkv + (size_t)(256 + h * 32) * N;
    const float* vb = qkv + (size_t)(512 + h * 32) * N;

#pragma unroll
    for (int r = 0; r < 2; r++) {
        int idx4 = tid + r * 256;
        int d = idx4 >> 4, nq = (idx4 & 15) * 4;
        float4 qv = *(const float4*)(qb + (size_t)d * N + nq);
        qv.x *= scale; qv.y *= scale; qv.z *= scale; qv.w *= scale;
        *(float4*)(&Qs[d][nq]) = qv;
    }

    int ty = tid >> 4, tx = tid & 15;   // rows ty*4+i; dims tx and tx+16
    float m_r[4] = {-1e30f, -1e30f, -1e30f, -1e30f};
    float l_r[4] = {0.f, 0.f, 0.f, 0.f};
    u64 acc2[4][2] = {};                // [row i][d-half], pairs along m (reduction)

    for (int m0 = 0; m0 < N; m0 += 64) {
#pragma unroll
        for (int r = 0; r < 2; r++) {
            int idx4 = tid + r * 256;
            int d = idx4 >> 4, mq = (idx4 & 15) * 4;
            *(float4*)(&Ks[d][mq]) = *(const float4*)(kb + (size_t)d * N + m0 + mq);
            *(float4*)(&Vs[d][mq]) = *(const float4*)(vb + (size_t)d * N + m0 + mq);
        }
        __syncthreads();

        // ---- S = Q^T K (pairs along query-row) ----
        u64 c2[2][4] = {};
#pragma unroll
        for (int d = 0; d < 32; d++) {
            ulonglong2 qq = *(const ulonglong2*)(&Qs[d][ty * 4]);  // (q0,q1),(q2,q3)
            float4 kf = *(const float4*)(&Ks[d][tx * 4]);
            u64 k0 = pack2(kf.x, kf.x), k1 = pack2(kf.y, kf.y);
            u64 k2 = pack2(kf.z, kf.z), k3 = pack2(kf.w, kf.w);
            ffma2(c2[0][0], qq.x, k0); ffma2(c2[0][1], qq.x, k1);
            ffma2(c2[0][2], qq.x, k2); ffma2(c2[0][3], qq.x, k3);
            ffma2(c2[1][0], qq.y, k0); ffma2(c2[1][1], qq.y, k1);
            ffma2(c2[1][2], qq.y, k2); ffma2(c2[1][3], qq.y, k3);
        }
        float c[4][4];
#pragma unroll
        for (int ipair = 0; ipair < 2; ipair++)
#pragma unroll
            for (int j = 0; j < 4; j++) {
                float2 v = unpack2(c2[ipair][j]);
                c[ipair * 2 + 0][j] = v.x;
                c[ipair * 2 + 1][j] = v.y;
            }

        // ---- register softmax: row r spread over 16 lanes (tx) ----
        float tm[4];
#pragma unroll
        for (int i = 0; i < 4; i++)
            tm[i] = fmaxf(fmaxf(c[i][0], c[i][1]), fmaxf(c[i][2], c[i][3]));
#pragma unroll
        for (int off = 1; off < 16; off <<= 1) {
#pragma unroll
            for (int i = 0; i < 4; i++)
                tm[i] = fmaxf(tm[i], __shfl_xor_sync(0xffffffffu, tm[i], off));
        }
        float corr[4];
#pragma unroll
        for (int i = 0; i < 4; i++) {
            float newm = fmaxf(m_r[i], tm[i]);
            corr[i] = fast_exp(m_r[i] - newm);
            m_r[i] = newm;
        }
#pragma unroll
        for (int i = 0; i < 4; i++)
#pragma unroll
            for (int j = 0; j < 4; j++)
                c[i][j] = fast_exp(c[i][j] - m_r[i]);
        float ts[4];
#pragma unroll
        for (int i = 0; i < 4; i++)
            ts[i] = (c[i][0] + c[i][1]) + (c[i][2] + c[i][3]);
#pragma unroll
        for (int off = 1; off < 16; off <<= 1) {
#pragma unroll
            for (int i = 0; i < 4; i++)
                ts[i] += __shfl_xor_sync(0xffffffffu, ts[i], off);
        }
#pragma unroll
        for (int i = 0; i < 4; i++) {
            l_r[i] = l_r[i] * corr[i] + ts[i];
            u64 cd = pack2(corr[i], corr[i]);
            fmul2(acc2[i][0], cd);
            fmul2(acc2[i][1], cd);
            *(float4*)(&S[ty * 4 + i][tx * 4]) = make_float4(c[i][0], c[i][1], c[i][2], c[i][3]);
        }
        __syncthreads();

        // ---- O += P V^T (pairs along m, fully packed both operands) ----
#pragma unroll
        for (int m4 = 0; m4 < 16; m4++) {
            ulonglong2 va  = *(const ulonglong2*)(&Vs[tx     ][m4 * 4]);
            ulonglong2 vb2 = *(const ulonglong2*)(&Vs[tx + 16][m4 * 4]);
#pragma unroll
            for (int i = 0; i < 4; i++) {
                ulonglong2 pp = *(const ulonglong2*)(&S[ty * 4 + i][m4 * 4]);
                ffma2(acc2[i][0], pp.x, va.x);  ffma2(acc2[i][0], pp.y, va.y);
                ffma2(acc2[i][1], pp.x, vb2.x); ffma2(acc2[i][1], pp.y, vb2.y);
            }
        }
        __syncthreads();
    }

    // ---- finalize: horizontal add, normalize, stage transposed, coalesced store ----
#pragma unroll
    for (int i = 0; i < 4; i++) {
        float inv = 1.0f / l_r[i];
        float2 s0 = unpack2(acc2[i][0]);
        float2 s1 = unpack2(acc2[i][1]);
        S[tx     ][ty * 4 + i] = (s0.x + s0.y) * inv;
        S[tx + 16][ty * 4 + i] = (s1.x + s1.y) * inv;
    }
    __syncthreads();
#pragma unroll
    for (int r = 0; r < 8; r++) {
        int idx = tid + r * 256;
        int d = idx >> 6, n = idx & 63;
        out[(size_t)(h * 32 + d) * N + n0 + n] = S[d][n];
    }
}

// ---------------- bilinear upsample (jax.image.resize semantics) ----------------
__global__ void upsample_kernel(const float* __restrict__ in, float* __restrict__ out,
                                int s, int Hs) {
    int idx = blockIdx.x * 256 + threadIdx.x;
    int xo = idx & 63, yo = (idx >> 6) & 63, c = idx >> 12;
    float fs = 1.0f / s;
    float fy = (yo + 0.5f) * fs - 0.5f;
    float fx = (xo + 0.5f) * fs - 0.5f;
    float fy0 = floorf(fy), fx0 = floorf(fx);
    float wy = fy - fy0, wx = fx - fx0;
    int y0 = (int)fy0, x0 = (int)fx0;
    int y0c = max(y0, 0), y1c = min(y0 + 1, Hs - 1);
    int x0c = max(x0, 0), x1c = min(x0 + 1, Hs - 1);
    const float* ip = in + (size_t)c * Hs * Hs;
    float v00 = ip[y0c * Hs + x0c], v01 = ip[y0c * Hs + x1c];
    float v10 = ip[y1c * Hs + x0c], v11 = ip[y1c * Hs + x1c];
    float v0 = v00 + (v01 - v00) * wx;
    float v1 = v10 + (v11 - v10) * wx;
    out[idx] = v0 + (v1 - v0) * wy;
}

// ---------------- host launch ----------------
extern "C" void kernel_launch(void* const* d_in, const int* in_sizes, int n_in,
                              void* d_out, int out_size) {
    const float* x     = (const float*)d_in[0];
    const float* dw_w  = (const float*)d_in[1];
    const float* dw_b  = (const float*)d_in[2];
    const float* pw_w  = (const float*)d_in[3];
    const float* pw_b  = (const float*)d_in[4];
    const float* pos_w = (const float*)d_in[5];
    const float* pos_b = (const float*)d_in[6];
    const float* fus_w = (const float*)d_in[7];
    const float* fus_b = (const float*)d_in[8];
    float* out = (float*)d_out;

    float *xs, *dw, *pos, *qkv, *att, *cat;
    cudaGetSymbolAddress((void**)&xs,  g_xs);
    cudaGetSymbolAddress((void**)&dw,  g_dw);
    cudaGetSymbolAddress((void**)&pos, g_pos);
    cudaGetSymbolAddress((void**)&qkv, g_qkv);
    cudaGetSymbolAddress((void**)&att, g_att);
    cudaGetSymbolAddress((void**)&cat, g_cat);

    const int scales[3] = {1, 2, 4};
    for (int i = 0; i < 3; i++) {
        int s  = scales[i];
        int Hs = HH / s;
        int Ns = Hs * Hs;
        const float* src = x;
        if (s > 1) {
            pool_kernel<<<(CC * Ns + 255) / 256, 256>>>(x, xs, s, Hs);
            src = xs;
        }
        dwconv_kernel<<<(CC * Ns) / 256, 256>>>(src,
                                                dw_w + i * CC * 9, dw_b + i * CC,
                                                pos_w + i * CC * 9, pos_b + i * CC,
                                                dw, pos, Hs);
        gemm_kernel<true><<<dim3(Ns / 64, 768 / 64), 256>>>(
            pw_w + (size_t)i * 768 * 256, dw, pw_b + i * 768, pos, qkv, 256, Ns);
        float* att_dst = (s == 1) ? cat : att;
        attn_kernel<<<dim3(Ns / 64, 8), 256>>>(qkv, att_dst, Ns);
        if (s > 1) {
            upsample_kernel<<<(CC * NPIX) / 256, 256>>>(att, cat + (size_t)i * CC * NPIX, s, Hs);
        }
    }
    gemm_kernel<false><<<dim3(NPIX / 64, CC / 64), 256>>>(
        fus_w, cat, fus_b, nullptr, out, 3 * CC, NPIX);
}